// round 17
// baseline (speedup 1.0000x reference)
#include <cuda_runtime.h>
#include <cstdint>

// RoIBridge round 17: phase-separated reads and writes.
// R16 falsified the store-issue theory (issue 9%, dur flat). All kernels
// plateau at ~4.43TB/s in-kernel store acceptance with nothing saturated.
// Remaining suspect: fine-grained read/write interleaving (each row's
// obj/frac LDG sits right before its 4KB of stores -> constant HBM/L2
// direction switching). Fix: each of 456 blocks owns a contiguous 576-row
// chunk; Phase 1 stages table (57.6KB) + the chunk's obj/frac (11.5KB) into
// smem; Phase 2 is a PURE-WRITE loop (no global loads at all):
// LDS scalars + LDS table gathers + st256 stores.
//  - smem 69.1KB -> 3 blocks/SM (207KB), 512 threads
//  - thread = (row-in-pass = tid>>3, 32B lane j = tid&7), 9 passes of 64 rows

static constexpr int IMAGE_SIZE = 224;
static constexpr int ROWS = 2048 * 128;       // 262144
static constexpr int TABLE_F4 = 225 * 16;     // 3600 float4 = 57600 B
static constexpr int NBLOCKS = 456;           // 152 SMs x 3
static constexpr int RPB = 576;               // rows per block (456*576 >= ROWS)
static constexpr int PASSES = RPB / 64;       // 9 (64 rows per pass @512 thr)

__device__ __forceinline__ int clamp_idx(float f) {
    float x = fminf(fmaxf(f * (float)IMAGE_SIZE, 0.0f), (float)IMAGE_SIZE);
    return (int)x;   // trunc toward zero == astype(int32), x >= 0
}

// 256-bit store: two float4, one instruction (sm_103a).
__device__ __forceinline__ void st256(float4* p, float4 a, float4 b) {
    asm volatile(
        "st.global.v8.f32 [%0], {%1,%2,%3,%4,%5,%6,%7,%8};"
        :: "l"(p),
           "f"(a.x), "f"(a.y), "f"(a.z), "f"(a.w),
           "f"(b.x), "f"(b.y), "f"(b.z), "f"(b.w)
        : "memory");
}

extern __shared__ unsigned char smem_raw[];
// layout: table[3600] float4 | frac[576] float4 | obj[576] int  = 69120 B

__global__ void __launch_bounds__(512, 3)
roibridge_kernel(const float4* __restrict__ frac4,   // [ROWS]
                 const int*    __restrict__ obj,     // [ROWS]
                 const float4* __restrict__ table4,  // [225*16]
                 float4*       __restrict__ out)     // [ROWS*64]
{
    float4* s_tab  = (float4*)smem_raw;            // [3600]
    float4* s_frac = s_tab + TABLE_F4;             // [576]
    int*    s_obj  = (int*)(s_frac + RPB);         // [576]

    const int tid  = threadIdx.x;
    const int base = blockIdx.x * RPB;

    // ---- Phase 1: stage table + this block's scalars (all reads) ----
    for (int i = tid; i < TABLE_F4; i += 512)
        s_tab[i] = table4[i];
    for (int i = tid; i < RPB; i += 512) {
        int r = base + i;
        if (r < ROWS) {
            s_frac[i] = __ldg(frac4 + r);
            s_obj[i]  = __ldg(obj + r);
        } else {
            s_obj[i] = 0;
        }
    }
    __syncthreads();

    // ---- Phase 2: pure-write loop (zero global loads) ----
    const int j2  = (tid & 7) * 2;   // float4 pair base within coord block
    const int rl0 = tid >> 3;        // row-in-pass 0..63

    const float4 z = make_float4(0.f, 0.f, 0.f, 0.f);

    #pragma unroll
    for (int pass = 0; pass < PASSES; ++pass) {
        const int rl = rl0 + pass * 64;
        const int r  = base + rl;
        if (r >= ROWS) break;

        float4* bp = out + (size_t)r * 64 + j2;

        if (s_obj[rl] == 1) {
            const float4 f = s_frac[rl];
            {   const float4* t = s_tab + clamp_idx(f.x) * 16 + j2;
                st256(bp +  0, t[0], t[1]); }
            {   const float4* t = s_tab + clamp_idx(f.y) * 16 + j2;
                st256(bp + 16, t[0], t[1]); }
            {   const float4* t = s_tab + clamp_idx(f.z) * 16 + j2;
                st256(bp + 32, t[0], t[1]); }
            {   const float4* t = s_tab + clamp_idx(f.w) * 16 + j2;
                st256(bp + 48, t[0], t[1]); }
        } else {
            st256(bp +  0, z, z);
            st256(bp + 16, z, z);
            st256(bp + 32, z, z);
            st256(bp + 48, z, z);
        }
    }
}

extern "C" void kernel_launch(void* const* d_in, const int* in_sizes, int n_in,
                              void* d_out, int out_size)
{
    const float4* frac4 = (const float4*)d_in[0];   // [2048,128,4] f32
    const int*    obj   = (const int*)d_in[1];      // [2048,128] i32
    const float4* table = (const float4*)d_in[2];   // [225,64] f32
    float4* out = (float4*)d_out;

    const int smem_bytes = TABLE_F4 * 16 + RPB * 16 + RPB * 4;  // 69120
    cudaFuncSetAttribute(roibridge_kernel,
                         cudaFuncAttributeMaxDynamicSharedMemorySize, smem_bytes);

    roibridge_kernel<<<NBLOCKS, 512, smem_bytes>>>(frac4, obj, table, out);
}